// round 10
// baseline (speedup 1.0000x reference)
#include <cuda_runtime.h>
#include <cuda_fp16.h>
#include <cstdint>

// Problem constants
#define TT 8
#define HH 64
#define WW 64
#define CC 256
#define HEADS 8
#define WS 7
#define NNB 147
#define NPIX (TT*HH*WW)                 // 32768
#define ATTN_ELEMS (HEADS*TT*HH*WW*NNB) // 38,535,168
#define PER_HEAD_FLOW (TT*HH*WW*NNB*3)  // 14,450,688
#define NW 512                          // W rows (2*CC)

// Scratch
__device__ float  g_q [(size_t)NPIX * CC];   // q fp32 [pix][256]
__device__ __half g_kh[(size_t)NPIX * CC];   // k fp16 [pix][256]
__device__ __half g_xh[(size_t)NPIX * CC];   // x hi
__device__ __half g_xl[(size_t)NPIX * CC];   // x lo
__device__ __half g_wh[(size_t)NW * CC];     // W hi
__device__ __half g_wl[(size_t)NW * CC];     // W lo

// ---------------- common helpers ----------------
__device__ __forceinline__ int reflect_idx(int idx) {
    int m = idx % 126;
    if (m < 0) m += 126;
    return (m > 63) ? (126 - m) : m;
}

__device__ __forceinline__ uint32_t h2_bits(__half2 v) {
    return *reinterpret_cast<uint32_t*>(&v);
}

__device__ __forceinline__ uint32_t smem_u32(const void* p) {
    uint32_t a;
    asm("{ .reg .u64 t; cvta.to.shared.u64 t, %1; cvt.u32.u64 %0, t; }" : "=r"(a) : "l"(p));
    return a;
}

__device__ __forceinline__ void cp16(uint32_t dst, const void* src) {
    asm volatile("cp.async.ca.shared.global [%0], [%1], 16;" :: "r"(dst), "l"(src));
}
#define CP_COMMIT() asm volatile("cp.async.commit_group;" ::: "memory")
#define CP_WAIT(n)  asm volatile("cp.async.wait_group %0;" :: "n"(n) : "memory")

#define LDSM4(r, a) \
    asm volatile("ldmatrix.sync.aligned.m8n8.x4.shared.b16 {%0,%1,%2,%3}, [%4];" \
                 : "=r"((r)[0]), "=r"((r)[1]), "=r"((r)[2]), "=r"((r)[3]) : "r"(a))

#define MMA16816(d, a, b0, b1) \
    asm volatile("mma.sync.aligned.m16n8k16.row.col.f32.f16.f16.f32 " \
                 "{%0,%1,%2,%3}, {%4,%5,%6,%7}, {%8,%9}, {%0,%1,%2,%3};" \
                 : "+f"((d)[0]), "+f"((d)[1]), "+f"((d)[2]), "+f"((d)[3]) \
                 : "r"((a)[0]), "r"((a)[1]), "r"((a)[2]), "r"((a)[3]), "r"(b0), "r"(b1))

// ---------------- Kernel 0: fp32 -> fp16 hi/lo split ----------------
#define NV4X ((NPIX*CC)/4)   // 2,097,152
#define NV4W ((NW*CC)/4)     // 32,768

__global__ __launch_bounds__(256)
void convert_split(const float* __restrict__ x, const float* __restrict__ Wm) {
    const int total = NV4X + NV4W;
    for (int i = blockIdx.x * blockDim.x + threadIdx.x; i < total; i += gridDim.x * blockDim.x) {
        const float4 v = (i < NV4X) ? ((const float4*)x)[i] : ((const float4*)Wm)[i - NV4X];
        __half2 h01 = __floats2half2_rn(v.x, v.y);
        __half2 h23 = __floats2half2_rn(v.z, v.w);
        float2 r01 = __half22float2(h01);
        float2 r23 = __half22float2(h23);
        __half2 l01 = __floats2half2_rn(v.x - r01.x, v.y - r01.y);
        __half2 l23 = __floats2half2_rn(v.z - r23.x, v.w - r23.y);
        uint2 hv = make_uint2(h2_bits(h01), h2_bits(h23));
        uint2 lv = make_uint2(h2_bits(l01), h2_bits(l23));
        if (i < NV4X) {
            ((uint2*)g_xh)[i] = hv;
            ((uint2*)g_xl)[i] = lv;
        } else {
            ((uint2*)g_wh)[i - NV4X] = hv;
            ((uint2*)g_wl)[i - NV4X] = lv;
        }
    }
}

// ---------------- Kernel 1: HMMA fp16-split GEMM ----------------
#define BM 128
#define BN 128
#define BK 32
#define NIT (CC/BK)                 // 8
#define PADH 40                     // halves per smem row (80B)
#define TILE_HALVES (128*PADH)
#define STAGE_HALVES (4*TILE_HALVES)
#define GSMEM (2*STAGE_HALVES*2)    // 81920 bytes

__device__ __forceinline__ void issue_stage(int it, int stage, int m0, int n0,
                                            uint32_t sbase, int tid) {
    const int kc = it * BK;
    const int r_lo = tid >> 2;
    const int c = (tid & 3) << 3;
#pragma unroll
    for (int q = 0; q < 8; q++) {
        const int tile = q >> 1;
        const int r = ((q & 1) << 6) + r_lo;
        const __half* src;
        if (tile == 0)      src = g_xh + (size_t)(m0 + r) * CC + kc + c;
        else if (tile == 1) src = g_xl + (size_t)(m0 + r) * CC + kc + c;
        else if (tile == 2) src = g_wh + (size_t)(n0 + r) * CC + kc + c;
        else                src = g_wl + (size_t)(n0 + r) * CC + kc + c;
        const uint32_t dst = sbase +
            (uint32_t)((stage * STAGE_HALVES + tile * TILE_HALVES + r * PADH + c) * 2);
        cp16(dst, src);
    }
}

__global__ __launch_bounds__(256)
void gemm_hmma(void) {
    extern __shared__ __half smem[];
    const uint32_t sbase = smem_u32(smem);
    const int tid = threadIdx.x;
    const int wid = tid >> 5;
    const int lane = tid & 31;

    const int n0 = blockIdx.x * BN;
    const int m0 = blockIdx.y * BM;
    const bool is_k = (n0 >= CC);

    const int wm = (wid >> 1) * 32;
    const int wn = (wid & 1) * 64;
    const int l15 = lane & 15;
    const int kofs = (lane >> 4) << 3;

    float acc[2][8][4];
#pragma unroll
    for (int i = 0; i < 2; i++)
#pragma unroll
        for (int j = 0; j < 8; j++)
#pragma unroll
            for (int c = 0; c < 4; c++) acc[i][j][c] = 0.0f;

    issue_stage(0, 0, m0, n0, sbase, tid);
    CP_COMMIT();

    for (int it = 0; it < NIT; it++) {
        if (it + 1 < NIT) {
            issue_stage(it + 1, (it + 1) & 1, m0, n0, sbase, tid);
            CP_COMMIT();
            CP_WAIT(1);
        } else {
            CP_WAIT(0);
        }
        __syncthreads();

        const uint32_t st = sbase + (uint32_t)(((it & 1) * STAGE_HALVES) * 2);
        const uint32_t ah_b = st;
        const uint32_t al_b = st + TILE_HALVES * 2;
        const uint32_t bh_b = st + 2 * TILE_HALVES * 2;
        const uint32_t bl_b = st + 3 * TILE_HALVES * 2;

#pragma unroll
        for (int kk = 0; kk < BK; kk += 16) {
            uint32_t ah[2][4], al[2][4];
#pragma unroll
            for (int mt = 0; mt < 2; mt++) {
                const uint32_t off = (uint32_t)(((wm + mt * 16 + l15) * PADH + kk + kofs) * 2);
                LDSM4(ah[mt], ah_b + off);
                LDSM4(al[mt], al_b + off);
            }
#pragma unroll
            for (int np = 0; np < 4; np++) {
                const uint32_t off = (uint32_t)(((wn + np * 16 + l15) * PADH + kk + kofs) * 2);
                uint32_t bh[4], bl[4];
                LDSM4(bh, bh_b + off);
                LDSM4(bl, bl_b + off);
#pragma unroll
                for (int mt = 0; mt < 2; mt++) {
                    MMA16816(acc[mt][2 * np],     ah[mt], bh[0], bh[2]);
                    MMA16816(acc[mt][2 * np + 1], ah[mt], bh[1], bh[3]);
                    MMA16816(acc[mt][2 * np],     ah[mt], bl[0], bl[2]);
                    MMA16816(acc[mt][2 * np + 1], ah[mt], bl[1], bl[3]);
                    MMA16816(acc[mt][2 * np],     al[mt], bh[0], bh[2]);
                    MMA16816(acc[mt][2 * np + 1], al[mt], bh[1], bh[3]);
                }
            }
        }
        __syncthreads();
    }

    const int r0 = m0 + wm + (lane >> 2);
    const int cbase = wn + ((lane & 3) << 1);
#pragma unroll
    for (int mt = 0; mt < 2; mt++) {
        const int row0 = r0 + mt * 16;
#pragma unroll
        for (int nt = 0; nt < 8; nt++) {
            const int col = n0 + cbase + nt * 8;
            float* a = acc[mt][nt];
            if (!is_k) {
                *(float2*)(g_q + (size_t)row0 * CC + col)       = make_float2(a[0], a[1]);
                *(float2*)(g_q + (size_t)(row0 + 8) * CC + col) = make_float2(a[2], a[3]);
            } else {
                __half2 h0 = __floats2half2_rn(a[0], a[1]);
                __half2 h1 = __floats2half2_rn(a[2], a[3]);
                *(uint32_t*)(g_kh + (size_t)row0 * CC + (col - CC))       = h2_bits(h0);
                *(uint32_t*)(g_kh + (size_t)(row0 + 8) * CC + (col - CC)) = h2_bits(h1);
            }
        }
    }
}

// ---------------- Kernel 2: attention scores (4x4 pixel tile, 16 warps) ----
#define SBUF_W 1184   // 1176 scores padded
#define ASMEM (16 * SBUF_W * 4)

__global__ __launch_bounds__(512)
void attn_kernel(const float* __restrict__ flows, float* __restrict__ out) {
    extern __shared__ float sbuf[];

    const int tidx = threadIdx.x;
    const int wid = tidx >> 5;
    const int lane = tidx & 31;

    const int t = blockIdx.z;
    const int h = blockIdx.y * 4 + (wid >> 2);
    const int w = blockIdx.x * 4 + (wid & 3);
    const int hw = h * WW + w;
    const int pix = t * (HH * WW) + hw;

    const float* qrow = g_q + (size_t)pix * CC;
    const float4 qa = ((const float4*)qrow)[lane * 2];
    const float4 qb = ((const float4*)qrow)[lane * 2 + 1];

    const int tp1 = (t + 1 < TT) ? t + 1 : t - 2;
    const int tp2 = (t - 1 >= 0) ? t - 1 : t + 2;

    const float f10 = flows[(4 * t + 0) * 4096 + hw];
    const float f11 = flows[(4 * t + 1) * 4096 + hw];
    const float f20 = flows[(4 * t + 2) * 4096 + hw];
    const float f21 = flows[(4 * t + 3) * 4096 + hw];

    const int tpr[3] = {t, tp1, tp2};
    const int dii[3] = {0, __float2int_rn(f10), __float2int_rn(f20)};
    const int djj[3] = {0, __float2int_rn(f11), __float2int_rn(f21)};

    float* srow = sbuf + wid * SBUF_W;

#pragma unroll
    for (int s = 0; s < 3; s++) {
        const __half* tslice = g_kh + (size_t)tpr[s] * (HH * WW) * CC;
        const int ci = h + dii[s];
        const int cj = w + djj[s];
        int ljo[WS];
#pragma unroll
        for (int b = 0; b < WS; b++) ljo[b] = reflect_idx(cj + b - 3) * CC;

        for (int a = 0; a < WS; a++) {
            const int li = reflect_idx(ci + a - 3);
            const __half* rbase = tslice + (size_t)li * WW * CC;
#pragma unroll
            for (int b = 0; b < WS; b++) {
                const uint4 kv = *(const uint4*)(rbase + ljo[b] + lane * 8);
                const float2 k0 = __half22float2(*reinterpret_cast<const __half2*>(&kv.x));
                const float2 k1 = __half22float2(*reinterpret_cast<const __half2*>(&kv.y));
                const float2 k2 = __half22float2(*reinterpret_cast<const __half2*>(&kv.z));
                const float2 k3 = __half22float2(*reinterpret_cast<const __half2*>(&kv.w));
                float p = qa.x * k0.x;
                p = fmaf(qa.y, k0.y, p);
                p = fmaf(qa.z, k1.x, p);
                p = fmaf(qa.w, k1.y, p);
                p = fmaf(qb.x, k2.x, p);
                p = fmaf(qb.y, k2.y, p);
                p = fmaf(qb.z, k3.x, p);
                p = fmaf(qb.w, k3.y, p);
                p += __shfl_xor_sync(0xffffffffu, p, 1);
                p += __shfl_xor_sync(0xffffffffu, p, 2);
                if ((lane & 3) == 0) {
                    srow[(lane >> 2) * NNB + s * 49 + a * 7 + b] = p;
                }
            }
        }
    }
    __syncwarp();

    const float scale = 0.17677669529663687f;
#pragma unroll
    for (int head = 0; head < HEADS; head++) {
        size_t obase = ((size_t)(head * TT + t) * (HH * WW) + hw) * (size_t)NNB;
        for (int i = lane; i < NNB; i += 32)
            out[obase + i] = srow[head * NNB + i] * scale;
    }
}

// ---------------- Kernel 3: flows_k writer ----------------
__global__ __launch_bounds__(256)
void flowsk_kernel(const float* __restrict__ flows, float* __restrict__ outF) {
    __shared__ float sbuf[8 * NNB * 3];

    const int pix0 = blockIdx.x * 8;
    const int tid = threadIdx.x;

    for (int e = tid; e < 8 * NNB * 3; e += 256) {
        const int lp = e / (NNB * 3);
        const int r = e - lp * (NNB * 3);
        const int n = r / 3;
        const int c = r - n * 3;
        const int pix = pix0 + lp;
        const int t = pix >> 12;
        const int hw = pix & 4095;
        const int h = hw >> 6;
        const int w = hw & 63;

        const int s = n / 49;
        const int wn = n - s * 49;
        const int a = wn / 7;
        const int b = wn - a * 7;

        int dt, di, dj;
        if (s == 0) {
            dt = 0; di = 0; dj = 0;
        } else if (s == 1) {
            dt = (t + 1 < TT) ? 1 : -2;
            di = __float2int_rn(flows[(4 * t + 0) * 4096 + hw]);
            dj = __float2int_rn(flows[(4 * t + 1) * 4096 + hw]);
        } else {
            dt = (t - 1 >= 0) ? -1 : 2;
            di = __float2int_rn(flows[(4 * t + 2) * 4096 + hw]);
            dj = __float2int_rn(flows[(4 * t + 3) * 4096 + hw]);
        }

        int v;
        if (c == 0)      v = dt;
        else if (c == 1) v = reflect_idx(h + di + a - 3) - h;
        else             v = reflect_idx(w + dj + b - 3) - w;
        sbuf[e] = (float)v;
    }
    __syncthreads();

    const float4* s4 = (const float4*)sbuf;
    const int nv4 = (8 * NNB * 3) / 4;
#pragma unroll
    for (int head = 0; head < HEADS; head++) {
        float4* dst = (float4*)(outF + (size_t)head * PER_HEAD_FLOW + (size_t)pix0 * (NNB * 3));
        for (int i = tid; i < nv4; i += 256) dst[i] = s4[i];
    }
}

// ---------------- launch ----------------
extern "C" void kernel_launch(void* const* d_in, const int* in_sizes, int n_in,
                              void* d_out, int out_size) {
    const float* x     = (const float*)d_in[0];
    const float* flows = (const float*)d_in[1];
    const float* Wm    = (const float*)d_in[2];
    float* out = (float*)d_out;

    cudaFuncSetAttribute(gemm_hmma, cudaFuncAttributeMaxDynamicSharedMemorySize, GSMEM);
    cudaFuncSetAttribute(attn_kernel, cudaFuncAttributeMaxDynamicSharedMemorySize, ASMEM);

    // Fork a side branch for the independent flows_k writer so it overlaps
    // convert+gemm in the captured graph (DRAM-bound vs tensor/L1-bound).
    cudaStream_t s2;
    cudaStreamCreateWithFlags(&s2, cudaStreamNonBlocking);
    cudaEvent_t e1, e2;
    cudaEventCreateWithFlags(&e1, cudaEventDisableTiming);
    cudaEventCreateWithFlags(&e2, cudaEventDisableTiming);

    cudaEventRecord(e1, 0);
    cudaStreamWaitEvent(s2, e1, 0);
    flowsk_kernel<<<NPIX / 8, 256, 0, s2>>>(flows, out + ATTN_ELEMS);
    cudaEventRecord(e2, s2);

    convert_split<<<1184, 256>>>(x, Wm);
    gemm_hmma<<<dim3(NW / BN, NPIX / BM), 256, GSMEM>>>();
    attn_kernel<<<dim3(WW / 4, HH / 4, TT), 512, ASMEM>>>(flows, out);

    cudaStreamWaitEvent(0, e2, 0);
    // Note: stream/events intentionally not destroyed here — kernel_launch is
    // invoked only for correctness + capture; destroying capture-forked
    // resources mid-capture is the riskier path.
}

// round 12
// speedup vs baseline: 1.0644x; 1.0644x over previous
#include <cuda_runtime.h>
#include <cuda_fp16.h>
#include <cstdint>

// Problem constants
#define TT 8
#define HH 64
#define WW 64
#define CC 256
#define HEADS 8
#define WS 7
#define NNB 147
#define NPIX (TT*HH*WW)                 // 32768
#define ATTN_ELEMS (HEADS*TT*HH*WW*NNB) // 38,535,168
#define PER_HEAD_FLOW (TT*HH*WW*NNB*3)  // 14,450,688
#define NW 512                          // W rows (2*CC)

// Scratch
__device__ float  g_q [(size_t)NPIX * CC];   // q fp32 [pix][256]
__device__ __half g_kh[(size_t)NPIX * CC];   // k fp16 [pix][256]
__device__ __half g_xh[(size_t)NPIX * CC];   // x hi
__device__ __half g_xl[(size_t)NPIX * CC];   // x lo
__device__ __half g_wh[(size_t)NW * CC];     // W hi
__device__ __half g_wl[(size_t)NW * CC];     // W lo

// ---------------- common helpers ----------------
__device__ __forceinline__ int reflect_idx(int idx) {
    int m = idx % 126;
    if (m < 0) m += 126;
    return (m > 63) ? (126 - m) : m;
}

__device__ __forceinline__ uint32_t h2_bits(__half2 v) {
    return *reinterpret_cast<uint32_t*>(&v);
}

__device__ __forceinline__ uint32_t smem_u32(const void* p) {
    uint32_t a;
    asm("{ .reg .u64 t; cvta.to.shared.u64 t, %1; cvt.u32.u64 %0, t; }" : "=r"(a) : "l"(p));
    return a;
}

__device__ __forceinline__ void cp16(uint32_t dst, const void* src) {
    asm volatile("cp.async.ca.shared.global [%0], [%1], 16;" :: "r"(dst), "l"(src));
}
#define CP_COMMIT() asm volatile("cp.async.commit_group;" ::: "memory")
#define CP_WAIT(n)  asm volatile("cp.async.wait_group %0;" :: "n"(n) : "memory")

#define LDSM4(r, a) \
    asm volatile("ldmatrix.sync.aligned.m8n8.x4.shared.b16 {%0,%1,%2,%3}, [%4];" \
                 : "=r"((r)[0]), "=r"((r)[1]), "=r"((r)[2]), "=r"((r)[3]) : "r"(a))

#define MMA16816(d, a, b0, b1) \
    asm volatile("mma.sync.aligned.m16n8k16.row.col.f32.f16.f16.f32 " \
                 "{%0,%1,%2,%3}, {%4,%5,%6,%7}, {%8,%9}, {%0,%1,%2,%3};" \
                 : "+f"((d)[0]), "+f"((d)[1]), "+f"((d)[2]), "+f"((d)[3]) \
                 : "r"((a)[0]), "r"((a)[1]), "r"((a)[2]), "r"((a)[3]), "r"(b0), "r"(b1))

// ---------------- Kernel 0: fp32 -> fp16 hi/lo split ----------------
#define NV4X ((NPIX*CC)/4)   // 2,097,152
#define NV4W ((NW*CC)/4)     // 32,768

__global__ __launch_bounds__(256)
void convert_split(const float* __restrict__ x, const float* __restrict__ Wm) {
    const int total = NV4X + NV4W;
    for (int i = blockIdx.x * blockDim.x + threadIdx.x; i < total; i += gridDim.x * blockDim.x) {
        const float4 v = (i < NV4X) ? ((const float4*)x)[i] : ((const float4*)Wm)[i - NV4X];
        __half2 h01 = __floats2half2_rn(v.x, v.y);
        __half2 h23 = __floats2half2_rn(v.z, v.w);
        float2 r01 = __half22float2(h01);
        float2 r23 = __half22float2(h23);
        __half2 l01 = __floats2half2_rn(v.x - r01.x, v.y - r01.y);
        __half2 l23 = __floats2half2_rn(v.z - r23.x, v.w - r23.y);
        uint2 hv = make_uint2(h2_bits(h01), h2_bits(h23));
        uint2 lv = make_uint2(h2_bits(l01), h2_bits(l23));
        if (i < NV4X) {
            ((uint2*)g_xh)[i] = hv;
            ((uint2*)g_xl)[i] = lv;
        } else {
            ((uint2*)g_wh)[i - NV4X] = hv;
            ((uint2*)g_wl)[i - NV4X] = lv;
        }
    }
}

// ---------------- Kernel 1: HMMA fp16-split GEMM ----------------
#define BM 128
#define BN 128
#define BK 32
#define NIT (CC/BK)                 // 8
#define PADH 40                     // halves per smem row (80B)
#define TILE_HALVES (128*PADH)
#define STAGE_HALVES (4*TILE_HALVES)
#define GSMEM (2*STAGE_HALVES*2)    // 81920 bytes

__device__ __forceinline__ void issue_stage(int it, int stage, int m0, int n0,
                                            uint32_t sbase, int tid) {
    const int kc = it * BK;
    const int r_lo = tid >> 2;
    const int c = (tid & 3) << 3;
#pragma unroll
    for (int q = 0; q < 8; q++) {
        const int tile = q >> 1;
        const int r = ((q & 1) << 6) + r_lo;
        const __half* src;
        if (tile == 0)      src = g_xh + (size_t)(m0 + r) * CC + kc + c;
        else if (tile == 1) src = g_xl + (size_t)(m0 + r) * CC + kc + c;
        else if (tile == 2) src = g_wh + (size_t)(n0 + r) * CC + kc + c;
        else                src = g_wl + (size_t)(n0 + r) * CC + kc + c;
        const uint32_t dst = sbase +
            (uint32_t)((stage * STAGE_HALVES + tile * TILE_HALVES + r * PADH + c) * 2);
        cp16(dst, src);
    }
}

__global__ __launch_bounds__(256)
void gemm_hmma(void) {
    extern __shared__ __half smem[];
    const uint32_t sbase = smem_u32(smem);
    const int tid = threadIdx.x;
    const int wid = tid >> 5;
    const int lane = tid & 31;

    const int n0 = blockIdx.x * BN;
    const int m0 = blockIdx.y * BM;
    const bool is_k = (n0 >= CC);

    const int wm = (wid >> 1) * 32;
    const int wn = (wid & 1) * 64;
    const int l15 = lane & 15;
    const int kofs = (lane >> 4) << 3;

    float acc[2][8][4];
#pragma unroll
    for (int i = 0; i < 2; i++)
#pragma unroll
        for (int j = 0; j < 8; j++)
#pragma unroll
            for (int c = 0; c < 4; c++) acc[i][j][c] = 0.0f;

    issue_stage(0, 0, m0, n0, sbase, tid);
    CP_COMMIT();

    for (int it = 0; it < NIT; it++) {
        if (it + 1 < NIT) {
            issue_stage(it + 1, (it + 1) & 1, m0, n0, sbase, tid);
            CP_COMMIT();
            CP_WAIT(1);
        } else {
            CP_WAIT(0);
        }
        __syncthreads();

        const uint32_t st = sbase + (uint32_t)(((it & 1) * STAGE_HALVES) * 2);
        const uint32_t ah_b = st;
        const uint32_t al_b = st + TILE_HALVES * 2;
        const uint32_t bh_b = st + 2 * TILE_HALVES * 2;
        const uint32_t bl_b = st + 3 * TILE_HALVES * 2;

#pragma unroll
        for (int kk = 0; kk < BK; kk += 16) {
            uint32_t ah[2][4], al[2][4];
#pragma unroll
            for (int mt = 0; mt < 2; mt++) {
                const uint32_t off = (uint32_t)(((wm + mt * 16 + l15) * PADH + kk + kofs) * 2);
                LDSM4(ah[mt], ah_b + off);
                LDSM4(al[mt], al_b + off);
            }
#pragma unroll
            for (int np = 0; np < 4; np++) {
                const uint32_t off = (uint32_t)(((wn + np * 16 + l15) * PADH + kk + kofs) * 2);
                uint32_t bh[4], bl[4];
                LDSM4(bh, bh_b + off);
                LDSM4(bl, bl_b + off);
#pragma unroll
                for (int mt = 0; mt < 2; mt++) {
                    MMA16816(acc[mt][2 * np],     ah[mt], bh[0], bh[2]);
                    MMA16816(acc[mt][2 * np + 1], ah[mt], bh[1], bh[3]);
                    MMA16816(acc[mt][2 * np],     ah[mt], bl[0], bl[2]);
                    MMA16816(acc[mt][2 * np + 1], ah[mt], bl[1], bl[3]);
                    MMA16816(acc[mt][2 * np],     al[mt], bh[0], bh[2]);
                    MMA16816(acc[mt][2 * np + 1], al[mt], bh[1], bh[3]);
                }
            }
        }
        __syncthreads();
    }

    const int r0 = m0 + wm + (lane >> 2);
    const int cbase = wn + ((lane & 3) << 1);
#pragma unroll
    for (int mt = 0; mt < 2; mt++) {
        const int row0 = r0 + mt * 16;
#pragma unroll
        for (int nt = 0; nt < 8; nt++) {
            const int col = n0 + cbase + nt * 8;
            float* a = acc[mt][nt];
            if (!is_k) {
                *(float2*)(g_q + (size_t)row0 * CC + col)       = make_float2(a[0], a[1]);
                *(float2*)(g_q + (size_t)(row0 + 8) * CC + col) = make_float2(a[2], a[3]);
            } else {
                __half2 h0 = __floats2half2_rn(a[0], a[1]);
                __half2 h1 = __floats2half2_rn(a[2], a[3]);
                *(uint32_t*)(g_kh + (size_t)row0 * CC + (col - CC))       = h2_bits(h0);
                *(uint32_t*)(g_kh + (size_t)(row0 + 8) * CC + (col - CC)) = h2_bits(h1);
            }
        }
    }
}

// ---------------- Kernel 2: attention scores (half2 math) + flows_k ----------
#define WBUF 1344   // per-warp smem floats (scores 1176 / flow expansion, reused)

__global__ __launch_bounds__(256)
void attn_kernel(const float* __restrict__ flows, float* __restrict__ out) {
    __shared__ float sbuf[8 * WBUF];
    __shared__ float mtab[8 * 48];   // per-warp mini tables: dt[3], diR[21], djR[21]

    const int tidx = threadIdx.x;
    const int wid = tidx >> 5;
    const int lane = tidx & 31;

    const int t = blockIdx.z;
    const int h = blockIdx.y * 4 + (wid >> 1);
    const int w = blockIdx.x * 2 + (wid & 1);
    const int hw = h * WW + w;
    const int pix = t * (HH * WW) + hw;

    // q quantized to fp16 (4 half2 = 8 dims per lane)
    const float* qrow = g_q + (size_t)pix * CC;
    const float4 qaf = ((const float4*)qrow)[lane * 2];
    const float4 qbf = ((const float4*)qrow)[lane * 2 + 1];
    const __half2 q0 = __floats2half2_rn(qaf.x, qaf.y);
    const __half2 q1 = __floats2half2_rn(qaf.z, qaf.w);
    const __half2 q2 = __floats2half2_rn(qbf.x, qbf.y);
    const __half2 q3 = __floats2half2_rn(qbf.z, qbf.w);

    const int tp1 = (t + 1 < TT) ? t + 1 : t - 2;
    const int tp2 = (t - 1 >= 0) ? t - 1 : t + 2;

    const float f10 = flows[(4 * t + 0) * 4096 + hw];
    const float f11 = flows[(4 * t + 1) * 4096 + hw];
    const float f20 = flows[(4 * t + 2) * 4096 + hw];
    const float f21 = flows[(4 * t + 3) * 4096 + hw];

    const int di1 = __float2int_rn(f10), dj1 = __float2int_rn(f11);
    const int di2 = __float2int_rn(f20), dj2 = __float2int_rn(f21);

    const int tpr[3] = {t, tp1, tp2};
    const int dii[3] = {0, di1, di2};
    const int djj[3] = {0, dj1, dj2};

    float* srow = sbuf + wid * WBUF;
    float* mt = mtab + wid * 48;

    // ---- fill per-pixel mini tables (45 values; strided over 32 lanes) ----
    for (int idx = lane; idx < 45; idx += 32) {
        float v;
        if (idx < 3) {
            const int dtv = (idx == 0) ? 0 : (idx == 1 ? ((t + 1 < TT) ? 1 : -2)
                                                       : ((t - 1 >= 0) ? -1 : 2));
            v = (float)dtv;
        } else if (idx < 24) {
            const int l = idx - 3;
            const int s = l / 7, a = l - s * 7;
            const int ds = (s == 0) ? 0 : (s == 1 ? di1 : di2);
            v = (float)(reflect_idx(h + ds + a - 3) - h);
        } else {
            const int l = idx - 24;
            const int s = l / 7, b = l - s * 7;
            const int ds = (s == 0) ? 0 : (s == 1 ? dj1 : dj2);
            v = (float)(reflect_idx(w + ds + b - 3) - w);
        }
        mt[idx] = v;
    }

    // ---- scores (half2 inner product, fp32 cross-lane reduce) ----
#pragma unroll
    for (int s = 0; s < 3; s++) {
        const __half* tslice = g_kh + (size_t)tpr[s] * (HH * WW) * CC;
        const int ci = h + dii[s];
        const int cj = w + djj[s];
        int ljo[WS];
#pragma unroll
        for (int b = 0; b < WS; b++) ljo[b] = reflect_idx(cj + b - 3) * CC;

        for (int a = 0; a < WS; a++) {
            const int li = reflect_idx(ci + a - 3);
            const __half* rbase = tslice + (size_t)li * WW * CC;
#pragma unroll
            for (int b = 0; b < WS; b++) {
                const uint4 kv = *(const uint4*)(rbase + ljo[b] + lane * 8);
                const __half2 k0 = *reinterpret_cast<const __half2*>(&kv.x);
                const __half2 k1 = *reinterpret_cast<const __half2*>(&kv.y);
                const __half2 k2 = *reinterpret_cast<const __half2*>(&kv.z);
                const __half2 k3 = *reinterpret_cast<const __half2*>(&kv.w);
                __half2 acc = __hmul2(q0, k0);
                acc = __hfma2(q1, k1, acc);
                acc = __hfma2(q2, k2, acc);
                acc = __hfma2(q3, k3, acc);
                const float2 f = __half22float2(acc);
                float p = f.x + f.y;
                p += __shfl_xor_sync(0xffffffffu, p, 1);
                p += __shfl_xor_sync(0xffffffffu, p, 2);
                if ((lane & 3) == 0) {
                    srow[(lane >> 2) * NNB + s * 49 + a * 7 + b] = p;
                }
            }
        }
    }
    __syncwarp();

    const float scale = 0.17677669529663687f;
#pragma unroll
    for (int head = 0; head < HEADS; head++) {
        size_t obase = ((size_t)(head * TT + t) * (HH * WW) + hw) * (size_t)NNB;
        for (int i = lane; i < NNB; i += 32)
            out[obase + i] = srow[head * NNB + i] * scale;
    }
    __syncwarp();

    // ---- flows_k: expand mini tables into srow (reused), then replicate x8 ----
    const int basef = pix * (NNB * 3);       // float offset within a head slab
    const int pad = basef & 3;               // store element e at srow[pad+e]
    for (int n = lane; n < NNB; n += 32) {
        const int s = (n >= 98) ? 2 : ((n >= 49) ? 1 : 0);
        const int r = n - s * 49;
        const int a = r / 7;
        const int b = r - a * 7;
        const int o = pad + 3 * n;
        srow[o]     = mt[s];
        srow[o + 1] = mt[3 + s * 7 + a];
        srow[o + 2] = mt[24 + s * 7 + b];
    }
    __syncwarp();

    float* outF = out + (size_t)ATTN_ELEMS;
    const int lead = (4 - pad) & 3;
    const int nv4 = (NNB * 3 - lead) >> 2;
    const int tail = (NNB * 3 - lead) & 3;
    const float4* s4 = (const float4*)(srow + pad + lead);
#pragma unroll
    for (int head = 0; head < HEADS; head++) {
        float* gp = outF + (size_t)head * PER_HEAD_FLOW + basef;
        if (lane < lead) gp[lane] = srow[pad + lane];
        float4* g4 = (float4*)(gp + lead);
        for (int i = lane; i < nv4; i += 32) g4[i] = s4[i];
        if (lane < tail) gp[lead + 4 * nv4 + lane] = srow[pad + lead + 4 * nv4 + lane];
    }
}

// ---------------- launch ----------------
extern "C" void kernel_launch(void* const* d_in, const int* in_sizes, int n_in,
                              void* d_out, int out_size) {
    const float* x     = (const float*)d_in[0];
    const float* flows = (const float*)d_in[1];
    const float* Wm    = (const float*)d_in[2];
    float* out = (float*)d_out;

    cudaFuncSetAttribute(gemm_hmma, cudaFuncAttributeMaxDynamicSharedMemorySize, GSMEM);

    convert_split<<<1184, 256>>>(x, Wm);
    gemm_hmma<<<dim3(NW / BN, NPIX / BM), 256, GSMEM>>>();
    attn_kernel<<<dim3(WW / 2, HH / 4, TT), 256>>>(flows, out);
}